// round 3
// baseline (speedup 1.0000x reference)
#include <cuda_runtime.h>
#include <math.h>

// Problem: B=2, N=1024, T=12, H=64, F=1
#define NB 1024
#define IMP_OFF  0
#define PRED_OFF 24576
#define REP_OFF  49152

// ---------------- persistent scratch (device globals; no runtime allocation) ------
__device__ __align__(16) float g_h   [2*64*NB];   // hidden state (B,H,N)
__device__ __align__(16) float g_E64 [4*64*NB];   // A_sb h
__device__ __align__(16) float g_F64 [4*64*NB];   // A_sb^2 h
__device__ __align__(16) float g_G64 [4*64*NB];   // A_sb (r*h)
__device__ __align__(16) float g_H64 [4*64*NB];   // A_sb^2 (r*h)
__device__ __align__(16) float g_Dx  [4*2*NB];    // A_sb [x1;m]
__device__ __align__(16) float g_Ex  [4*2*NB];    // A_sb [x2;m]
__device__ __align__(16) float g_Fx  [4*2*NB];    // A_sb^2 [x2;m]
__device__ __align__(16) float g_u   [2*64*NB];   // update gate
__device__ __align__(16) float g_rh  [2*64*NB];   // r*h
__device__ __align__(16) float g_z1  [2*2*NB];    // [x1 ; m]  (B,2,N)
__device__ __align__(16) float g_z2  [2*2*NB];    // [x2 ; m]  (B,2,N)
__device__ __align__(16) float g_rs  [4*NB];      // rowsums of A_sb
__device__ __align__(16) float g_rep [12*2*128*NB]; // staged representations (t,b,2H,N)
// transposed weights [k][c]
__device__ __align__(16) float g_Wlout_t[128*64];
__device__ __align__(16) float g_Wr_t   [330*64];
__device__ __align__(16) float g_Wu_t   [330*64];
__device__ __align__(16) float g_Wc_t   [330*64];
__device__ __align__(16) float g_M_t    [2*66*64];  // (Wgc_s @ Wdin)^T  [s][j][c]
__device__ __align__(16) float g_vb     [2*64];     // Wgc_s @ bdin

__global__ void init_h_kernel()
{
    int i = blockIdx.x * 256 + threadIdx.x;
    if (i < 2*64*NB) g_h[i] = 0.f;
}

__global__ void prep_weights_kernel(const float* __restrict__ Wr,
                                    const float* __restrict__ Wu,
                                    const float* __restrict__ Wc,
                                    const float* __restrict__ Wlout)
{
    int idx = blockIdx.x * 256 + threadIdx.x;
    if (idx >= 330*64) return;
    int j = idx >> 6;     // k (column of original)
    int i = idx & 63;     // c (row of original)
    g_Wr_t[idx] = Wr[i*330 + j];
    g_Wu_t[idx] = Wu[i*330 + j];
    g_Wc_t[idx] = Wc[i*330 + j];
    if (j < 128) g_Wlout_t[idx] = Wlout[i*128 + j];
}

// M_s = Wgc[:, s*64:(s+1)*64] @ Wdin  (64x66), stored transposed [j][c]
// vb_s = Wgc_s @ bdin
__global__ void prep_M_kernel(const float* __restrict__ Wgc,
                              const float* __restrict__ Wdin,
                              const float* __restrict__ bdin)
{
    const int s = blockIdx.y;
    int idx = blockIdx.x * 256 + threadIdx.x;
    if (idx < 66*64) {
        int j = idx >> 6, c = idx & 63;
        float acc = 0.f;
        for (int k = 0; k < 64; k++)
            acc += Wgc[c*128 + s*64 + k] * Wdin[k*66 + j];
        g_M_t[s*66*64 + idx] = acc;
    } else if (idx < 66*64 + 64) {
        int c = idx - 66*64;
        float acc = 0.f;
        for (int k = 0; k < 64; k++)
            acc += Wgc[c*128 + s*64 + k] * bdin[k];
        g_vb[s*64 + c] = acc;
    }
}

// rowsums: g_rs[sb][w] = sum_v A[sb][w][v]
__global__ __launch_bounds__(256) void rowsum_kernel(const float* __restrict__ adj)
{
    const int sb = blockIdx.y;
    const int warp = threadIdx.x >> 5, lane = threadIdx.x & 31;
    const int w = blockIdx.x * 8 + warp;
    const float* Arow = adj + (size_t)sb*1048576 + (size_t)w*1024;
    float a = 0.f;
    #pragma unroll 4
    for (int v = lane; v < 1024; v += 32) a += Arow[v];
    #pragma unroll
    for (int off = 16; off; off >>= 1) a += __shfl_down_sync(0xffffffffu, a, off);
    if (lane == 0) g_rs[sb*1024 + w] = a;
}

// =====================================================================================
// Big diffusion: O[sb][c][w] = sum_v Z[.][c][v] * A[sb][w][v]
// BM=64 x BN=16 x BK=64, 128 threads, double-buffered smem, 4x2 acc per thread.
// grid (64, 4) = 256 blocks.  stage 0: h->E  1: E->F  2: rh->G  3: G->H
// =====================================================================================
__global__ __launch_bounds__(128) void diffuse64_kernel(const float* __restrict__ adj, int stage)
{
    const int sb = blockIdx.y;
    const int w0 = blockIdx.x * 16;
    const float* Z; float* O;
    switch (stage) {
        case 0:  Z = g_h   + (sb&1)*65536; O = g_E64 + sb*65536; break;
        case 1:  Z = g_E64 + sb*65536;     O = g_F64 + sb*65536; break;
        case 2:  Z = g_rh  + (sb&1)*65536; O = g_G64 + sb*65536; break;
        default: Z = g_G64 + sb*65536;     O = g_H64 + sb*65536; break;
    }
    const float* A = adj + (size_t)sb*1048576 + (size_t)w0*1024;
    const int tid = threadIdx.x;

    __shared__ float Zs[2][64][68];
    __shared__ float As[2][64][20];

    const int zc = tid >> 1;          // 0..63 channel
    const int zk = (tid & 1) * 32;    // + j*4, j=0..7
    const int aw = tid >> 3;          // 0..15 w
    const int ak = (tid & 7) * 4;     // + j*32, j=0..1

    float4 rz[8], ra[2];

    // tile 0 loads
    #pragma unroll
    for (int j = 0; j < 8; j++) rz[j] = *(const float4*)&Z[zc*1024 + zk + j*4];
    #pragma unroll
    for (int j = 0; j < 2; j++) ra[j] = *(const float4*)&A[aw*1024 + ak + j*32];
    #pragma unroll
    for (int j = 0; j < 8; j++) {
        int k = zk + j*4;
        Zs[0][k+0][zc] = rz[j].x; Zs[0][k+1][zc] = rz[j].y;
        Zs[0][k+2][zc] = rz[j].z; Zs[0][k+3][zc] = rz[j].w;
    }
    #pragma unroll
    for (int j = 0; j < 2; j++) {
        int k = ak + j*32;
        As[0][k+0][aw] = ra[j].x; As[0][k+1][aw] = ra[j].y;
        As[0][k+2][aw] = ra[j].z; As[0][k+3][aw] = ra[j].w;
    }
    __syncthreads();

    const int cb = (tid >> 3) * 4;   // 0..60
    const int wb = (tid & 7) * 2;    // 0..14
    float acc[4][2] = {};

    int buf = 0;
    for (int kt = 0; kt < 16; kt++) {
        if (kt < 15) {
            const int v0 = (kt + 1) * 64;
            #pragma unroll
            for (int j = 0; j < 8; j++) rz[j] = *(const float4*)&Z[zc*1024 + v0 + zk + j*4];
            #pragma unroll
            for (int j = 0; j < 2; j++) ra[j] = *(const float4*)&A[aw*1024 + v0 + ak + j*32];
        }
        #pragma unroll
        for (int k = 0; k < 64; k++) {
            float4 z = *(const float4*)&Zs[buf][k][cb];
            float2 a = *(const float2*)&As[buf][k][wb];
            acc[0][0] += z.x*a.x; acc[0][1] += z.x*a.y;
            acc[1][0] += z.y*a.x; acc[1][1] += z.y*a.y;
            acc[2][0] += z.z*a.x; acc[2][1] += z.z*a.y;
            acc[3][0] += z.w*a.x; acc[3][1] += z.w*a.y;
        }
        if (kt < 15) {
            const int nb2 = buf ^ 1;
            #pragma unroll
            for (int j = 0; j < 8; j++) {
                int k = zk + j*4;
                Zs[nb2][k+0][zc] = rz[j].x; Zs[nb2][k+1][zc] = rz[j].y;
                Zs[nb2][k+2][zc] = rz[j].z; Zs[nb2][k+3][zc] = rz[j].w;
            }
            #pragma unroll
            for (int j = 0; j < 2; j++) {
                int k = ak + j*32;
                As[nb2][k+0][aw] = ra[j].x; As[nb2][k+1][aw] = ra[j].y;
                As[nb2][k+2][aw] = ra[j].z; As[nb2][k+3][aw] = ra[j].w;
            }
        }
        __syncthreads();
        buf ^= 1;
    }
    #pragma unroll
    for (int i = 0; i < 4; i++) {
        *(float2*)&O[(size_t)(cb+i)*1024 + w0 + wb] = make_float2(acc[i][0], acc[i][1]);
    }
}

// =====================================================================================
// 2-channel diffusion. stage 0: z1->Dx  1: z2->Ex  2: Ex->Fx
// grid (128, 4), 256 threads: one w per warp, lanes over v + warp reduce.
// =====================================================================================
__global__ __launch_bounds__(256) void diffuse2_kernel(const float* __restrict__ adj, int stage)
{
    const int sb = blockIdx.y;
    __shared__ float zs[2][NB];
    const float* src;
    if      (stage == 0) src = g_z1 + (sb&1)*2048;
    else if (stage == 1) src = g_z2 + (sb&1)*2048;
    else                 src = g_Ex + sb*2048;
    for (int i = threadIdx.x; i < 2048; i += 256) zs[i >> 10][i & 1023] = src[i];
    __syncthreads();

    const int warp = threadIdx.x >> 5, lane = threadIdx.x & 31;
    const int w = blockIdx.x * 8 + warp;
    const float* Arow = adj + (size_t)sb*1048576 + (size_t)w*1024;
    float a0 = 0.f, a1 = 0.f;
    #pragma unroll 4
    for (int v = lane; v < 1024; v += 32) {
        float av = Arow[v];
        a0 += av * zs[0][v];
        a1 += av * zs[1][v];
    }
    #pragma unroll
    for (int off = 16; off; off >>= 1) {
        a0 += __shfl_down_sync(0xffffffffu, a0, off);
        a1 += __shfl_down_sync(0xffffffffu, a1, off);
    }
    if (lane == 0) {
        float* dst;
        if      (stage == 0) dst = g_Dx + sb*2048;
        else if (stage == 1) dst = g_Ex + sb*2048;
        else                 dst = g_Fx + sb*2048;
        dst[w]        = a0;
        dst[1024 + w] = a1;
    }
}

#define FMA42(acc, w4, v2) do { \
    acc[0][0] += (w4).x*(v2).x; acc[0][1] += (w4).x*(v2).y; \
    acc[1][0] += (w4).y*(v2).x; acc[1][1] += (w4).y*(v2).y; \
    acc[2][0] += (w4).z*(v2).x; acc[2][1] += (w4).z*(v2).y; \
    acc[3][0] += (w4).w*(v2).x; acc[3][1] += (w4).w*(v2).y; } while (0)

// =====================================================================================
// pre kernel: xs1 = Wfs.h + bfs ; preds out ; x1 = m?x:xs1 ; z1 = [x1;m]
// grid 64 (b x ntile32), 32 threads
// =====================================================================================
__global__ __launch_bounds__(32) void pre_kernel(const float* __restrict__ x,
                                                 const int*   __restrict__ mask,
                                                 const float* __restrict__ Wfs,
                                                 const float* __restrict__ bfs,
                                                 float* __restrict__ out, int t)
{
    const int b  = blockIdx.x >> 5;
    const int nn = (blockIdx.x & 31) * 32 + threadIdx.x;
    float s = bfs[0];
    #pragma unroll 8
    for (int c = 0; c < 64; c++) s += Wfs[c] * g_h[b*65536 + c*1024 + nn];
    out[PRED_OFF + (b*1024 + nn)*12 + t] = s;
    int m = mask[b*12288 + nn*12 + t];
    float xv = x[b*12288 + nn*12 + t];
    float x1 = m ? xv : s;
    g_z1[b*2048 + nn]        = x1;
    g_z1[b*2048 + 1024 + nn] = (float)m;
}

// =====================================================================================
// decoder: out = M0.[Dx0;E0] + M1.[Dx1;E1] + vb0*rs0 + vb1*rs1 + bgc
//          out = prelu(Wlout.[out;h]+blout) ; repr=[out;h] ; xs2=Wro.repr+bro
//          imps out ; z2 = [m?x1:xs2 ; m]
// =====================================================================================
__global__ __launch_bounds__(256) void decoder_kernel(const float* __restrict__ bgc,
                                                      const float* __restrict__ blout,
                                                      const float* __restrict__ Wro,
                                                      const float* __restrict__ bro,
                                                      const float* __restrict__ prelu_a,
                                                      const int*   __restrict__ mask,
                                                      float* __restrict__ out, int t)
{
    const int b  = blockIdx.x >> 5;
    const int n0 = (blockIdx.x & 31) * 32;
    const int tid = threadIdx.x;
    __shared__ float E0s[64][36];
    __shared__ float E1s[64][36];
    __shared__ float Hs[64][36];
    __shared__ float Gs[64][36];
    __shared__ float Os[64][36];
    __shared__ float DXs[2][2][36];
    __shared__ float RSs[2][36];

    for (int i = tid; i < 64*32; i += 256) {
        int r = i >> 5, n = i & 31;
        E0s[r][n] = g_E64[b*65536       + r*1024 + n0 + n];
        E1s[r][n] = g_E64[(2+b)*65536   + r*1024 + n0 + n];
        Hs[r][n]  = g_h  [b*65536       + r*1024 + n0 + n];
    }
    if (tid < 128) {
        int s = tid >> 6, ch = (tid >> 5) & 1, n = tid & 31;
        DXs[s][ch][n] = g_Dx[(s*2 + b)*2048 + ch*1024 + n0 + n];
    } else if (tid < 192) {
        int idx = tid - 128; int s = idx >> 5, n = idx & 31;
        RSs[s][n] = g_rs[(s*2 + b)*1024 + n0 + n];
    }
    __syncthreads();

    const int ty = tid >> 4, tx = tid & 15;
    const int cbv = ty*4, nbv = tx*2;
    float acc[4][2] = {};
    #pragma unroll
    for (int s = 0; s < 2; s++) {
        const float* Mt = g_M_t + s*66*64;
        {
            float4 w0 = *(const float4*)&Mt[0*64 + cbv];
            float2 v0 = *(const float2*)&DXs[s][0][nbv];
            FMA42(acc, w0, v0);
            float4 w1 = *(const float4*)&Mt[1*64 + cbv];
            float2 v1 = *(const float2*)&DXs[s][1][nbv];
            FMA42(acc, w1, v1);
        }
        #pragma unroll 4
        for (int k = 0; k < 64; k++) {
            float4 w = *(const float4*)&Mt[(2+k)*64 + cbv];
            float2 v = s ? *(const float2*)&E1s[k][nbv] : *(const float2*)&E0s[k][nbv];
            FMA42(acc, w, v);
        }
    }
    #pragma unroll
    for (int i = 0; i < 4; i++) {
        int c = cbv + i;
        float v0 = g_vb[c], v1 = g_vb[64 + c], bv = bgc[c];
        Gs[c][nbv]   = acc[i][0] + v0*RSs[0][nbv]   + v1*RSs[1][nbv]   + bv;
        Gs[c][nbv+1] = acc[i][1] + v0*RSs[0][nbv+1] + v1*RSs[1][nbv+1] + bv;
    }
    __syncthreads();

    float acc2[4][2] = {};
    #pragma unroll 4
    for (int k = 0; k < 64; k++) {
        float4 w = *(const float4*)&g_Wlout_t[k*64 + cbv];
        float2 v = *(const float2*)&Gs[k][nbv];
        FMA42(acc2, w, v);
    }
    #pragma unroll 4
    for (int k = 0; k < 64; k++) {
        float4 w = *(const float4*)&g_Wlout_t[(64+k)*64 + cbv];
        float2 v = *(const float2*)&Hs[k][nbv];
        FMA42(acc2, w, v);
    }
    const float pa = prelu_a[0];
    #pragma unroll
    for (int i = 0; i < 4; i++) {
        int c = cbv + i;
        float bv = blout[c];
        float o0 = acc2[i][0] + bv; if (o0 < 0.f) o0 *= pa;
        float o1 = acc2[i][1] + bv; if (o1 < 0.f) o1 *= pa;
        Os[c][nbv] = o0; Os[c][nbv+1] = o1;
        *(float2*)&g_rep[((size_t)(t*2 + b)*128 + c)*1024 + n0 + nbv] = make_float2(o0, o1);
    }
    __syncthreads();

    for (int i = tid; i < 64*32; i += 256) {
        int c = i >> 5, n = i & 31;
        g_rep[((size_t)(t*2 + b)*128 + 64 + c)*1024 + n0 + n] = Hs[c][n];
    }
    if (tid < 32) {
        const int n = tid, nn = n0 + n;
        float s = bro[0];
        #pragma unroll 8
        for (int c = 0; c < 64; c++) s += Wro[c]*Os[c][n] + Wro[64+c]*Hs[c][n];
        out[IMP_OFF + (b*1024 + nn)*12 + t] = s;
        int m = mask[b*12288 + nn*12 + t];
        float x2 = m ? g_z1[b*2048 + nn] : s;
        g_z2[b*2048 + nn]        = x2;
        g_z2[b*2048 + 1024 + nn] = (float)m;
    }
}

// =====================================================================================
// V330 loader for gate/candidate. base64: h or rh.
// Row map (330): [z2(2), base64(64)] , per support s: [ex(2), d1(64), fx(2), d2(64)]
// =====================================================================================
__device__ __forceinline__ void load_V330(float (*Vs)[36], int b, int n0, int tid,
                                          const float* base64)
{
    for (int i = tid; i < 330*32; i += 256) {
        int r = i >> 5, n = i & 31;
        const float* src;
        const int sb0 = b, sb1 = 2 + b;
        if      (r < 2)   src = g_z2   + b*2048    + r*1024;
        else if (r < 66)  src = base64 + b*65536   + (r-2)*1024;
        else if (r < 68)  src = g_Ex   + sb0*2048  + (r-66)*1024;
        else if (r < 132) src = (base64 == g_h ? g_E64 : g_G64) + sb0*65536 + (r-68)*1024;
        else if (r < 134) src = g_Fx   + sb0*2048  + (r-132)*1024;
        else if (r < 198) src = (base64 == g_h ? g_F64 : g_H64) + sb0*65536 + (r-134)*1024;
        else if (r < 200) src = g_Ex   + sb1*2048  + (r-198)*1024;
        else if (r < 264) src = (base64 == g_h ? g_E64 : g_G64) + sb1*65536 + (r-200)*1024;
        else if (r < 266) src = g_Fx   + sb1*2048  + (r-264)*1024;
        else              src = (base64 == g_h ? g_F64 : g_H64) + sb1*65536 + (r-266)*1024;
        Vs[r][n] = src[n0 + n];
    }
}

__global__ __launch_bounds__(256) void gates_kernel(const float* __restrict__ br,
                                                    const float* __restrict__ bu)
{
    const int b  = blockIdx.x >> 5;
    const int n0 = (blockIdx.x & 31) * 32;
    const int tid = threadIdx.x;
    __shared__ float Vs[330][36];
    load_V330(Vs, b, n0, tid, g_h);
    __syncthreads();

    const int ty = tid >> 4, tx = tid & 15;
    const int cbv = ty*4, nbv = tx*2;
    float ar[4][2] = {}, au[4][2] = {};
    #pragma unroll 3
    for (int k = 0; k < 330; k++) {
        float4 wr = *(const float4*)&g_Wr_t[k*64 + cbv];
        float4 wu = *(const float4*)&g_Wu_t[k*64 + cbv];
        float2 v  = *(const float2*)&Vs[k][nbv];
        FMA42(ar, wr, v);
        FMA42(au, wu, v);
    }
    #pragma unroll
    for (int i = 0; i < 4; i++) {
        const int c = cbv + i;
        const float brv = br[c], buv = bu[c];
        float2 h2 = *(const float2*)&g_h[b*65536 + c*1024 + n0 + nbv];
        float r0 = 1.f / (1.f + expf(-(ar[i][0] + brv)));
        float r1 = 1.f / (1.f + expf(-(ar[i][1] + brv)));
        float u0 = 1.f / (1.f + expf(-(au[i][0] + buv)));
        float u1 = 1.f / (1.f + expf(-(au[i][1] + buv)));
        *(float2*)&g_u [b*65536 + c*1024 + n0 + nbv] = make_float2(u0, u1);
        *(float2*)&g_rh[b*65536 + c*1024 + n0 + nbv] = make_float2(r0*h2.x, r1*h2.y);
    }
}

__global__ __launch_bounds__(256) void cand_kernel(const float* __restrict__ bc)
{
    const int b  = blockIdx.x >> 5;
    const int n0 = (blockIdx.x & 31) * 32;
    const int tid = threadIdx.x;
    __shared__ float Vs[330][36];
    load_V330(Vs, b, n0, tid, g_rh);
    __syncthreads();

    const int ty = tid >> 4, tx = tid & 15;
    const int cbv = ty*4, nbv = tx*2;
    float acc[4][2] = {};
    #pragma unroll 4
    for (int k = 0; k < 330; k++) {
        float4 w = *(const float4*)&g_Wc_t[k*64 + cbv];
        float2 v = *(const float2*)&Vs[k][nbv];
        FMA42(acc, w, v);
    }
    #pragma unroll
    for (int i = 0; i < 4; i++) {
        const int c = cbv + i;
        const float bv = bc[c];
        const size_t idx = (size_t)b*65536 + c*1024 + n0 + nbv;
        float2 h2 = *(const float2*)&g_h[idx];
        float2 u2 = *(const float2*)&g_u[idx];
        float c0 = tanhf(acc[i][0] + bv);
        float c1 = tanhf(acc[i][1] + bv);
        *(float2*)&g_h[idx] = make_float2(u2.x*h2.x + (1.f-u2.x)*c0,
                                          u2.y*h2.y + (1.f-u2.y)*c1);
    }
}

// Final transpose of staged representations: out[b][cc][n][t] = g_rep[t][b][cc][n]
__global__ __launch_bounds__(256) void rep_out_kernel(float* __restrict__ out)
{
    const int bc = blockIdx.x;               // 0..255 = b*128+cc
    const int b = bc >> 7, cc = bc & 127;
    __shared__ float s[12][NB];
    for (int i = threadIdx.x; i < 12*NB; i += 256) {
        int t = i >> 10, n = i & 1023;
        s[t][n] = g_rep[((size_t)(t*2 + b)*128 + cc)*1024 + n];
    }
    __syncthreads();
    float* dst = out + REP_OFF + (size_t)bc * 12288;
    for (int i = threadIdx.x; i < 12288; i += 256) {
        int n = i / 12, t = i - n*12;
        dst[i] = s[t][n];
    }
}

extern "C" void kernel_launch(void* const* d_in, const int* in_sizes, int n_in,
                              void* d_out, int out_size)
{
    const float* x     = (const float*)d_in[0];
    const int*   mask  = (const int*)  d_in[1];
    const float* adj   = (const float*)d_in[2];
    const float* Wr    = (const float*)d_in[3];
    const float* br    = (const float*)d_in[4];
    const float* Wu    = (const float*)d_in[5];
    const float* bu    = (const float*)d_in[6];
    const float* Wc    = (const float*)d_in[7];
    const float* bc    = (const float*)d_in[8];
    const float* Wfs   = (const float*)d_in[9];
    const float* bfs   = (const float*)d_in[10];
    const float* Wdin  = (const float*)d_in[11];
    const float* bdin  = (const float*)d_in[12];
    const float* Wgc   = (const float*)d_in[13];
    const float* bgc   = (const float*)d_in[14];
    const float* Wlout = (const float*)d_in[15];
    const float* blout = (const float*)d_in[16];
    const float* Wro   = (const float*)d_in[17];
    const float* bro   = (const float*)d_in[18];
    const float* pa    = (const float*)d_in[19];
    float* out = (float*)d_out;

    init_h_kernel<<<512, 256>>>();
    prep_weights_kernel<<<83, 256>>>(Wr, Wu, Wc, Wlout);
    prep_M_kernel<<<dim3(17,2), 256>>>(Wgc, Wdin, bdin);
    rowsum_kernel<<<dim3(128,4), 256>>>(adj);

    for (int t = 0; t < 12; t++) {
        pre_kernel<<<64, 32>>>(x, mask, Wfs, bfs, out, t);
        diffuse2_kernel<<<dim3(128,4), 256>>>(adj, 0);          // Dx
        diffuse64_kernel<<<dim3(64,4), 128>>>(adj, 0);          // E = A h
        diffuse64_kernel<<<dim3(64,4), 128>>>(adj, 1);          // F = A E
        decoder_kernel<<<64, 256>>>(bgc, blout, Wro, bro, pa, mask, out, t);
        diffuse2_kernel<<<dim3(128,4), 256>>>(adj, 1);          // Ex
        diffuse2_kernel<<<dim3(128,4), 256>>>(adj, 2);          // Fx
        gates_kernel<<<64, 256>>>(br, bu);
        diffuse64_kernel<<<dim3(64,4), 128>>>(adj, 2);          // G = A rh
        diffuse64_kernel<<<dim3(64,4), 128>>>(adj, 3);          // H = A G
        cand_kernel<<<64, 256>>>(bc);
    }
    rep_out_kernel<<<256, 256>>>(out);
}

// round 4
// speedup vs baseline: 1.1161x; 1.1161x over previous
#include <cuda_runtime.h>
#include <math.h>

// Problem: B=2, N=1024, T=12, H=64, F=1
#define NB 1024
#define IMP_OFF  0
#define PRED_OFF 24576
#define REP_OFF  49152

// ---------------- persistent scratch (device globals; no runtime allocation) ------
__device__ __align__(16) float g_h   [2*64*NB];   // hidden state (B,H,N)
__device__ __align__(16) float g_E64 [4*64*NB];   // A_sb h
__device__ __align__(16) float g_F64 [4*64*NB];   // A_sb^2 h
__device__ __align__(16) float g_G64 [4*64*NB];   // A_sb (r*h)
__device__ __align__(16) float g_H64 [4*64*NB];   // A_sb^2 (r*h)
__device__ __align__(16) float g_Dx  [4*2*NB];    // A_sb [x1;m]
__device__ __align__(16) float g_Ex  [4*2*NB];    // A_sb [x2;m]
__device__ __align__(16) float g_Fx  [4*2*NB];    // A_sb^2 [x2;m]
__device__ __align__(16) float g_u   [2*64*NB];   // update gate
__device__ __align__(16) float g_rh  [2*64*NB];   // r*h
__device__ __align__(16) float g_z1  [2*2*NB];    // [x1 ; m]  (B,2,N)
__device__ __align__(16) float g_z2  [2*2*NB];    // [x2 ; m]  (B,2,N)
__device__ __align__(16) float g_rs  [4*NB];      // rowsums of A_sb
__device__ __align__(16) float g_rep [12*2*128*NB]; // staged representations (t,b,2H,N)
// transposed weights [k][c]
__device__ __align__(16) float g_Wlout_t[128*64];
__device__ __align__(16) float g_Wr_t   [330*64];
__device__ __align__(16) float g_Wu_t   [330*64];
__device__ __align__(16) float g_Wc_t   [330*64];
__device__ __align__(16) float g_M_t    [2*66*64];  // (Wgc_s @ Wdin)^T  [s][j][c]
__device__ __align__(16) float g_vb     [2*64];     // Wgc_s @ bdin

__global__ void init_h_kernel()
{
    int i = blockIdx.x * 256 + threadIdx.x;
    if (i < 2*64*NB) g_h[i] = 0.f;
}

__global__ void prep_weights_kernel(const float* __restrict__ Wr,
                                    const float* __restrict__ Wu,
                                    const float* __restrict__ Wc,
                                    const float* __restrict__ Wlout)
{
    int idx = blockIdx.x * 256 + threadIdx.x;
    if (idx >= 330*64) return;
    int j = idx >> 6;     // k (column of original)
    int i = idx & 63;     // c (row of original)
    g_Wr_t[idx] = Wr[i*330 + j];
    g_Wu_t[idx] = Wu[i*330 + j];
    g_Wc_t[idx] = Wc[i*330 + j];
    if (j < 128) g_Wlout_t[idx] = Wlout[i*128 + j];
}

// M_s = Wgc[:, s*64:(s+1)*64] @ Wdin  (64x66), stored transposed [j][c]
// vb_s = Wgc_s @ bdin
__global__ void prep_M_kernel(const float* __restrict__ Wgc,
                              const float* __restrict__ Wdin,
                              const float* __restrict__ bdin)
{
    const int s = blockIdx.y;
    int idx = blockIdx.x * 256 + threadIdx.x;
    if (idx < 66*64) {
        int j = idx >> 6, c = idx & 63;
        float acc = 0.f;
        for (int k = 0; k < 64; k++)
            acc += Wgc[c*128 + s*64 + k] * Wdin[k*66 + j];
        g_M_t[s*66*64 + idx] = acc;
    } else if (idx < 66*64 + 64) {
        int c = idx - 66*64;
        float acc = 0.f;
        for (int k = 0; k < 64; k++)
            acc += Wgc[c*128 + s*64 + k] * bdin[k];
        g_vb[s*64 + c] = acc;
    }
}

// rowsums: g_rs[sb][w] = sum_v A[sb][w][v]
__global__ __launch_bounds__(256) void rowsum_kernel(const float* __restrict__ adj)
{
    const int sb = blockIdx.y;
    const int warp = threadIdx.x >> 5, lane = threadIdx.x & 31;
    const int w = blockIdx.x * 8 + warp;
    const float* Arow = adj + (size_t)sb*1048576 + (size_t)w*1024;
    float a = 0.f;
    #pragma unroll 4
    for (int v = lane; v < 1024; v += 32) a += Arow[v];
    #pragma unroll
    for (int off = 16; off; off >>= 1) a += __shfl_down_sync(0xffffffffu, a, off);
    if (lane == 0) g_rs[sb*1024 + w] = a;
}

// =====================================================================================
// Big diffusion: O[sb][c][w] = sum_v Z[.][c][v] * A[sb][w][v]
// BM=64 x BN=32 x BK=32, 256 threads (8 warps/SM), grid (32,4)=128 blocks,
// double-buffered smem, 4x2 acc per thread.
// stage 0: h->E  1: E->F  2: rh->G  3: G->H
// =====================================================================================
__global__ __launch_bounds__(256) void diffuse64_kernel(const float* __restrict__ adj, int stage)
{
    const int sb = blockIdx.y;
    const int w0 = blockIdx.x * 32;
    const float* Z; float* O;
    switch (stage) {
        case 0:  Z = g_h   + (sb&1)*65536; O = g_E64 + sb*65536; break;
        case 1:  Z = g_E64 + sb*65536;     O = g_F64 + sb*65536; break;
        case 2:  Z = g_rh  + (sb&1)*65536; O = g_G64 + sb*65536; break;
        default: Z = g_G64 + sb*65536;     O = g_H64 + sb*65536; break;
    }
    const float* A = adj + (size_t)sb*1048576 + (size_t)w0*1024;
    const int tid = threadIdx.x;

    __shared__ float Zs[2][32][68];
    __shared__ float As[2][32][34];

    const int zc = tid & 63;          // channel 0..63
    const int zk = (tid >> 6) * 8;    // v-offset base: two float4s
    const int aw = tid >> 3;          // 0..31 w
    const int ak = (tid & 7) * 4;     // one float4

    float4 rz0, rz1, ra;

    // tile 0 loads
    rz0 = *(const float4*)&Z[zc*1024 + zk];
    rz1 = *(const float4*)&Z[zc*1024 + zk + 4];
    ra  = *(const float4*)&A[aw*1024 + ak];
    Zs[0][zk+0][zc] = rz0.x; Zs[0][zk+1][zc] = rz0.y;
    Zs[0][zk+2][zc] = rz0.z; Zs[0][zk+3][zc] = rz0.w;
    Zs[0][zk+4][zc] = rz1.x; Zs[0][zk+5][zc] = rz1.y;
    Zs[0][zk+6][zc] = rz1.z; Zs[0][zk+7][zc] = rz1.w;
    As[0][ak+0][aw] = ra.x; As[0][ak+1][aw] = ra.y;
    As[0][ak+2][aw] = ra.z; As[0][ak+3][aw] = ra.w;
    __syncthreads();

    const int cb = (tid >> 4) * 4;   // 0..60
    const int wb = (tid & 15) * 2;   // 0..30
    float acc[4][2] = {};

    int buf = 0;
    for (int kt = 0; kt < 32; kt++) {
        if (kt < 31) {
            const int v0 = (kt + 1) * 32;
            rz0 = *(const float4*)&Z[zc*1024 + v0 + zk];
            rz1 = *(const float4*)&Z[zc*1024 + v0 + zk + 4];
            ra  = *(const float4*)&A[aw*1024 + v0 + ak];
        }
        #pragma unroll
        for (int k = 0; k < 32; k++) {
            float4 z = *(const float4*)&Zs[buf][k][cb];
            float2 a = *(const float2*)&As[buf][k][wb];
            acc[0][0] += z.x*a.x; acc[0][1] += z.x*a.y;
            acc[1][0] += z.y*a.x; acc[1][1] += z.y*a.y;
            acc[2][0] += z.z*a.x; acc[2][1] += z.z*a.y;
            acc[3][0] += z.w*a.x; acc[3][1] += z.w*a.y;
        }
        if (kt < 31) {
            const int nb2 = buf ^ 1;
            Zs[nb2][zk+0][zc] = rz0.x; Zs[nb2][zk+1][zc] = rz0.y;
            Zs[nb2][zk+2][zc] = rz0.z; Zs[nb2][zk+3][zc] = rz0.w;
            Zs[nb2][zk+4][zc] = rz1.x; Zs[nb2][zk+5][zc] = rz1.y;
            Zs[nb2][zk+6][zc] = rz1.z; Zs[nb2][zk+7][zc] = rz1.w;
            As[nb2][ak+0][aw] = ra.x; As[nb2][ak+1][aw] = ra.y;
            As[nb2][ak+2][aw] = ra.z; As[nb2][ak+3][aw] = ra.w;
        }
        __syncthreads();
        buf ^= 1;
    }
    #pragma unroll
    for (int i = 0; i < 4; i++) {
        *(float2*)&O[(size_t)(cb+i)*1024 + w0 + wb] = make_float2(acc[i][0], acc[i][1]);
    }
}

// =====================================================================================
// 2-channel diffusion. stage 0: z1->Dx  1: z2->Ex  2: Ex->Fx
// grid (128, 4), 256 threads: one w per warp, lanes over v + warp reduce.
// =====================================================================================
__global__ __launch_bounds__(256) void diffuse2_kernel(const float* __restrict__ adj, int stage)
{
    const int sb = blockIdx.y;
    __shared__ float zs[2][NB];
    const float* src;
    if      (stage == 0) src = g_z1 + (sb&1)*2048;
    else if (stage == 1) src = g_z2 + (sb&1)*2048;
    else                 src = g_Ex + sb*2048;
    for (int i = threadIdx.x; i < 2048; i += 256) zs[i >> 10][i & 1023] = src[i];
    __syncthreads();

    const int warp = threadIdx.x >> 5, lane = threadIdx.x & 31;
    const int w = blockIdx.x * 8 + warp;
    const float* Arow = adj + (size_t)sb*1048576 + (size_t)w*1024;
    float a0 = 0.f, a1 = 0.f;
    #pragma unroll 4
    for (int v = lane; v < 1024; v += 32) {
        float av = Arow[v];
        a0 += av * zs[0][v];
        a1 += av * zs[1][v];
    }
    #pragma unroll
    for (int off = 16; off; off >>= 1) {
        a0 += __shfl_down_sync(0xffffffffu, a0, off);
        a1 += __shfl_down_sync(0xffffffffu, a1, off);
    }
    if (lane == 0) {
        float* dst;
        if      (stage == 0) dst = g_Dx + sb*2048;
        else if (stage == 1) dst = g_Ex + sb*2048;
        else                 dst = g_Fx + sb*2048;
        dst[w]        = a0;
        dst[1024 + w] = a1;
    }
}

#define FMA42(acc, w4, v2) do { \
    acc[0][0] += (w4).x*(v2).x; acc[0][1] += (w4).x*(v2).y; \
    acc[1][0] += (w4).y*(v2).x; acc[1][1] += (w4).y*(v2).y; \
    acc[2][0] += (w4).z*(v2).x; acc[2][1] += (w4).z*(v2).y; \
    acc[3][0] += (w4).w*(v2).x; acc[3][1] += (w4).w*(v2).y; } while (0)

// =====================================================================================
// pre kernel: xs1 = Wfs.h + bfs ; preds out ; x1 = m?x:xs1 ; z1 = [x1;m]
// =====================================================================================
__global__ __launch_bounds__(32) void pre_kernel(const float* __restrict__ x,
                                                 const int*   __restrict__ mask,
                                                 const float* __restrict__ Wfs,
                                                 const float* __restrict__ bfs,
                                                 float* __restrict__ out, int t)
{
    const int b  = blockIdx.x >> 5;
    const int nn = (blockIdx.x & 31) * 32 + threadIdx.x;
    float s = bfs[0];
    #pragma unroll 8
    for (int c = 0; c < 64; c++) s += Wfs[c] * g_h[b*65536 + c*1024 + nn];
    out[PRED_OFF + (b*1024 + nn)*12 + t] = s;
    int m = mask[b*12288 + nn*12 + t];
    float xv = x[b*12288 + nn*12 + t];
    float x1 = m ? xv : s;
    g_z1[b*2048 + nn]        = x1;
    g_z1[b*2048 + 1024 + nn] = (float)m;
}

// =====================================================================================
// decoder: out = M0.[Dx0;E0] + M1.[Dx1;E1] + vb0*rs0 + vb1*rs1 + bgc
//          out = prelu(Wlout.[out;h]+blout) ; repr=[out;h] ; xs2=Wro.repr+bro
//          imps out ; z2 = [m?x1:xs2 ; m]
// =====================================================================================
__global__ __launch_bounds__(256) void decoder_kernel(const float* __restrict__ bgc,
                                                      const float* __restrict__ blout,
                                                      const float* __restrict__ Wro,
                                                      const float* __restrict__ bro,
                                                      const float* __restrict__ prelu_a,
                                                      const int*   __restrict__ mask,
                                                      float* __restrict__ out, int t)
{
    const int b  = blockIdx.x >> 5;
    const int n0 = (blockIdx.x & 31) * 32;
    const int tid = threadIdx.x;
    __shared__ float E0s[64][36];
    __shared__ float E1s[64][36];
    __shared__ float Hs[64][36];
    __shared__ float Gs[64][36];
    __shared__ float Os[64][36];
    __shared__ float DXs[2][2][36];
    __shared__ float RSs[2][36];

    for (int i = tid; i < 64*32; i += 256) {
        int r = i >> 5, n = i & 31;
        E0s[r][n] = g_E64[b*65536       + r*1024 + n0 + n];
        E1s[r][n] = g_E64[(2+b)*65536   + r*1024 + n0 + n];
        Hs[r][n]  = g_h  [b*65536       + r*1024 + n0 + n];
    }
    if (tid < 128) {
        int s = tid >> 6, ch = (tid >> 5) & 1, n = tid & 31;
        DXs[s][ch][n] = g_Dx[(s*2 + b)*2048 + ch*1024 + n0 + n];
    } else if (tid < 192) {
        int idx = tid - 128; int s = idx >> 5, n = idx & 31;
        RSs[s][n] = g_rs[(s*2 + b)*1024 + n0 + n];
    }
    __syncthreads();

    const int ty = tid >> 4, tx = tid & 15;
    const int cbv = ty*4, nbv = tx*2;
    float acc[4][2] = {};
    #pragma unroll
    for (int s = 0; s < 2; s++) {
        const float* Mt = g_M_t + s*66*64;
        {
            float4 w0 = *(const float4*)&Mt[0*64 + cbv];
            float2 v0 = *(const float2*)&DXs[s][0][nbv];
            FMA42(acc, w0, v0);
            float4 w1 = *(const float4*)&Mt[1*64 + cbv];
            float2 v1 = *(const float2*)&DXs[s][1][nbv];
            FMA42(acc, w1, v1);
        }
        #pragma unroll 4
        for (int k = 0; k < 64; k++) {
            float4 w = *(const float4*)&Mt[(2+k)*64 + cbv];
            float2 v = s ? *(const float2*)&E1s[k][nbv] : *(const float2*)&E0s[k][nbv];
            FMA42(acc, w, v);
        }
    }
    #pragma unroll
    for (int i = 0; i < 4; i++) {
        int c = cbv + i;
        float v0 = g_vb[c], v1 = g_vb[64 + c], bv = bgc[c];
        Gs[c][nbv]   = acc[i][0] + v0*RSs[0][nbv]   + v1*RSs[1][nbv]   + bv;
        Gs[c][nbv+1] = acc[i][1] + v0*RSs[0][nbv+1] + v1*RSs[1][nbv+1] + bv;
    }
    __syncthreads();

    float acc2[4][2] = {};
    #pragma unroll 4
    for (int k = 0; k < 64; k++) {
        float4 w = *(const float4*)&g_Wlout_t[k*64 + cbv];
        float2 v = *(const float2*)&Gs[k][nbv];
        FMA42(acc2, w, v);
    }
    #pragma unroll 4
    for (int k = 0; k < 64; k++) {
        float4 w = *(const float4*)&g_Wlout_t[(64+k)*64 + cbv];
        float2 v = *(const float2*)&Hs[k][nbv];
        FMA42(acc2, w, v);
    }
    const float pa = prelu_a[0];
    #pragma unroll
    for (int i = 0; i < 4; i++) {
        int c = cbv + i;
        float bv = blout[c];
        float o0 = acc2[i][0] + bv; if (o0 < 0.f) o0 *= pa;
        float o1 = acc2[i][1] + bv; if (o1 < 0.f) o1 *= pa;
        Os[c][nbv] = o0; Os[c][nbv+1] = o1;
        *(float2*)&g_rep[((size_t)(t*2 + b)*128 + c)*1024 + n0 + nbv] = make_float2(o0, o1);
    }
    __syncthreads();

    for (int i = tid; i < 64*32; i += 256) {
        int c = i >> 5, n = i & 31;
        g_rep[((size_t)(t*2 + b)*128 + 64 + c)*1024 + n0 + n] = Hs[c][n];
    }
    if (tid < 32) {
        const int n = tid, nn = n0 + n;
        float s = bro[0];
        #pragma unroll 8
        for (int c = 0; c < 64; c++) s += Wro[c]*Os[c][n] + Wro[64+c]*Hs[c][n];
        out[IMP_OFF + (b*1024 + nn)*12 + t] = s;
        int m = mask[b*12288 + nn*12 + t];
        float x2 = m ? g_z1[b*2048 + nn] : s;
        g_z2[b*2048 + nn]        = x2;
        g_z2[b*2048 + 1024 + nn] = (float)m;
    }
}

// =====================================================================================
// V330 loader for gate/candidate. base64: h or rh.
// Row map (330): [z2(2), base64(64)] , per support s: [ex(2), d1(64), fx(2), d2(64)]
// =====================================================================================
__device__ __forceinline__ void load_V330(float (*Vs)[36], int b, int n0, int tid,
                                          const float* base64)
{
    for (int i = tid; i < 330*32; i += 256) {
        int r = i >> 5, n = i & 31;
        const float* src;
        const int sb0 = b, sb1 = 2 + b;
        if      (r < 2)   src = g_z2   + b*2048    + r*1024;
        else if (r < 66)  src = base64 + b*65536   + (r-2)*1024;
        else if (r < 68)  src = g_Ex   + sb0*2048  + (r-66)*1024;
        else if (r < 132) src = (base64 == g_h ? g_E64 : g_G64) + sb0*65536 + (r-68)*1024;
        else if (r < 134) src = g_Fx   + sb0*2048  + (r-132)*1024;
        else if (r < 198) src = (base64 == g_h ? g_F64 : g_H64) + sb0*65536 + (r-134)*1024;
        else if (r < 200) src = g_Ex   + sb1*2048  + (r-198)*1024;
        else if (r < 264) src = (base64 == g_h ? g_E64 : g_G64) + sb1*65536 + (r-200)*1024;
        else if (r < 266) src = g_Fx   + sb1*2048  + (r-264)*1024;
        else              src = (base64 == g_h ? g_F64 : g_H64) + sb1*65536 + (r-266)*1024;
        Vs[r][n] = src[n0 + n];
    }
}

__global__ __launch_bounds__(256) void gates_kernel(const float* __restrict__ br,
                                                    const float* __restrict__ bu)
{
    const int b  = blockIdx.x >> 5;
    const int n0 = (blockIdx.x & 31) * 32;
    const int tid = threadIdx.x;
    __shared__ float Vs[330][36];
    load_V330(Vs, b, n0, tid, g_h);
    __syncthreads();

    const int ty = tid >> 4, tx = tid & 15;
    const int cbv = ty*4, nbv = tx*2;
    float ar[4][2] = {}, au[4][2] = {};
    #pragma unroll 3
    for (int k = 0; k < 330; k++) {
        float4 wr = *(const float4*)&g_Wr_t[k*64 + cbv];
        float4 wu = *(const float4*)&g_Wu_t[k*64 + cbv];
        float2 v  = *(const float2*)&Vs[k][nbv];
        FMA42(ar, wr, v);
        FMA42(au, wu, v);
    }
    #pragma unroll
    for (int i = 0; i < 4; i++) {
        const int c = cbv + i;
        const float brv = br[c], buv = bu[c];
        float2 h2 = *(const float2*)&g_h[b*65536 + c*1024 + n0 + nbv];
        float r0 = 1.f / (1.f + expf(-(ar[i][0] + brv)));
        float r1 = 1.f / (1.f + expf(-(ar[i][1] + brv)));
        float u0 = 1.f / (1.f + expf(-(au[i][0] + buv)));
        float u1 = 1.f / (1.f + expf(-(au[i][1] + buv)));
        *(float2*)&g_u [b*65536 + c*1024 + n0 + nbv] = make_float2(u0, u1);
        *(float2*)&g_rh[b*65536 + c*1024 + n0 + nbv] = make_float2(r0*h2.x, r1*h2.y);
    }
}

__global__ __launch_bounds__(256) void cand_kernel(const float* __restrict__ bc)
{
    const int b  = blockIdx.x >> 5;
    const int n0 = (blockIdx.x & 31) * 32;
    const int tid = threadIdx.x;
    __shared__ float Vs[330][36];
    load_V330(Vs, b, n0, tid, g_rh);
    __syncthreads();

    const int ty = tid >> 4, tx = tid & 15;
    const int cbv = ty*4, nbv = tx*2;
    float acc[4][2] = {};
    #pragma unroll 4
    for (int k = 0; k < 330; k++) {
        float4 w = *(const float4*)&g_Wc_t[k*64 + cbv];
        float2 v = *(const float2*)&Vs[k][nbv];
        FMA42(acc, w, v);
    }
    #pragma unroll
    for (int i = 0; i < 4; i++) {
        const int c = cbv + i;
        const float bv = bc[c];
        const size_t idx = (size_t)b*65536 + c*1024 + n0 + nbv;
        float2 h2 = *(const float2*)&g_h[idx];
        float2 u2 = *(const float2*)&g_u[idx];
        float c0 = tanhf(acc[i][0] + bv);
        float c1 = tanhf(acc[i][1] + bv);
        *(float2*)&g_h[idx] = make_float2(u2.x*h2.x + (1.f-u2.x)*c0,
                                          u2.y*h2.y + (1.f-u2.y)*c1);
    }
}

// Final transpose of staged representations: out[b][cc][n][t] = g_rep[t][b][cc][n]
__global__ __launch_bounds__(256) void rep_out_kernel(float* __restrict__ out)
{
    const int bc = blockIdx.x;               // 0..255 = b*128+cc
    const int b = bc >> 7, cc = bc & 127;
    __shared__ float s[12][NB];
    for (int i = threadIdx.x; i < 12*NB; i += 256) {
        int t = i >> 10, n = i & 1023;
        s[t][n] = g_rep[((size_t)(t*2 + b)*128 + cc)*1024 + n];
    }
    __syncthreads();
    float* dst = out + REP_OFF + (size_t)bc * 12288;
    for (int i = threadIdx.x; i < 12288; i += 256) {
        int n = i / 12, t = i - n*12;
        dst[i] = s[t][n];
    }
}

extern "C" void kernel_launch(void* const* d_in, const int* in_sizes, int n_in,
                              void* d_out, int out_size)
{
    const float* x     = (const float*)d_in[0];
    const int*   mask  = (const int*)  d_in[1];
    const float* adj   = (const float*)d_in[2];
    const float* Wr    = (const float*)d_in[3];
    const float* br    = (const float*)d_in[4];
    const float* Wu    = (const float*)d_in[5];
    const float* bu    = (const float*)d_in[6];
    const float* Wc    = (const float*)d_in[7];
    const float* bc    = (const float*)d_in[8];
    const float* Wfs   = (const float*)d_in[9];
    const float* bfs   = (const float*)d_in[10];
    const float* Wdin  = (const float*)d_in[11];
    const float* bdin  = (const float*)d_in[12];
    const float* Wgc   = (const float*)d_in[13];
    const float* bgc   = (const float*)d_in[14];
    const float* Wlout = (const float*)d_in[15];
    const float* blout = (const float*)d_in[16];
    const float* Wro   = (const float*)d_in[17];
    const float* bro   = (const float*)d_in[18];
    const float* pa    = (const float*)d_in[19];
    float* out = (float*)d_out;

    init_h_kernel<<<512, 256>>>();
    prep_weights_kernel<<<83, 256>>>(Wr, Wu, Wc, Wlout);
    prep_M_kernel<<<dim3(17,2), 256>>>(Wgc, Wdin, bdin);
    rowsum_kernel<<<dim3(128,4), 256>>>(adj);

    for (int t = 0; t < 12; t++) {
        pre_kernel<<<64, 32>>>(x, mask, Wfs, bfs, out, t);
        diffuse2_kernel<<<dim3(128,4), 256>>>(adj, 0);          // Dx
        diffuse64_kernel<<<dim3(32,4), 256>>>(adj, 0);          // E = A h
        diffuse64_kernel<<<dim3(32,4), 256>>>(adj, 1);          // F = A E
        decoder_kernel<<<64, 256>>>(bgc, blout, Wro, bro, pa, mask, out, t);
        diffuse2_kernel<<<dim3(128,4), 256>>>(adj, 1);          // Ex
        diffuse2_kernel<<<dim3(128,4), 256>>>(adj, 2);          // Fx
        gates_kernel<<<64, 256>>>(br, bu);
        diffuse64_kernel<<<dim3(32,4), 256>>>(adj, 2);          // G = A rh
        diffuse64_kernel<<<dim3(32,4), 256>>>(adj, 3);          // H = A G
        cand_kernel<<<64, 256>>>(bc);
    }
    rep_out_kernel<<<256, 256>>>(out);
}

// round 5
// speedup vs baseline: 1.2293x; 1.1014x over previous
#include <cuda_runtime.h>
#include <math.h>

// Problem: B=2, N=1024, T=12, H=64, F=1
#define NB 1024
#define IMP_OFF  0
#define PRED_OFF 24576
#define REP_OFF  49152

// ---------------- persistent scratch (device globals; no runtime allocation) ------
__device__ __align__(16) float g_h   [2*64*NB];   // hidden state (B,H,N)
__device__ __align__(16) float g_E64 [4*64*NB];   // A_sb h
__device__ __align__(16) float g_F64 [4*64*NB];   // A_sb^2 h
__device__ __align__(16) float g_G64 [4*64*NB];   // A_sb (r*h)
__device__ __align__(16) float g_H64 [4*64*NB];   // A_sb^2 (r*h)
__device__ __align__(16) float g_Dx  [4*2*NB];    // A_sb [x1;m]
__device__ __align__(16) float g_Ex  [4*2*NB];    // A_sb [x2;m]
__device__ __align__(16) float g_Fx  [4*2*NB];    // A_sb^2 [x2;m]
__device__ __align__(16) float g_u   [2*64*NB];   // update gate
__device__ __align__(16) float g_rh  [2*64*NB];   // r*h
__device__ __align__(16) float g_z1  [2*2*NB];    // [x1 ; m]  (B,2,N)
__device__ __align__(16) float g_z2  [2*2*NB];    // [x2 ; m]  (B,2,N)
__device__ __align__(16) float g_rs  [4*NB];      // rowsums of A_sb
__device__ __align__(16) float g_rep [12*2*128*NB]; // staged representations (t,b,2H,N)
// transposed weights [k][c]
__device__ __align__(16) float g_Wlout_t[128*64];
__device__ __align__(16) float g_Wr_t   [330*64];
__device__ __align__(16) float g_Wu_t   [330*64];
__device__ __align__(16) float g_Wc_t   [330*64];
__device__ __align__(16) float g_M_t    [2*66*64];  // (Wgc_s @ Wdin)^T  [s][j][c]
__device__ __align__(16) float g_vb     [2*64];     // Wgc_s @ bdin

__global__ void init_h_kernel()
{
    int i = blockIdx.x * 256 + threadIdx.x;
    if (i < 2*64*NB) g_h[i] = 0.f;
}

__global__ void prep_weights_kernel(const float* __restrict__ Wr,
                                    const float* __restrict__ Wu,
                                    const float* __restrict__ Wc,
                                    const float* __restrict__ Wlout)
{
    int idx = blockIdx.x * 256 + threadIdx.x;
    if (idx >= 330*64) return;
    int j = idx >> 6;     // k (column of original)
    int i = idx & 63;     // c (row of original)
    g_Wr_t[idx] = Wr[i*330 + j];
    g_Wu_t[idx] = Wu[i*330 + j];
    g_Wc_t[idx] = Wc[i*330 + j];
    if (j < 128) g_Wlout_t[idx] = Wlout[i*128 + j];
}

// M_s = Wgc[:, s*64:(s+1)*64] @ Wdin  (64x66), stored transposed [j][c]
// vb_s = Wgc_s @ bdin
__global__ void prep_M_kernel(const float* __restrict__ Wgc,
                              const float* __restrict__ Wdin,
                              const float* __restrict__ bdin)
{
    const int s = blockIdx.y;
    int idx = blockIdx.x * 256 + threadIdx.x;
    if (idx < 66*64) {
        int j = idx >> 6, c = idx & 63;
        float acc = 0.f;
        for (int k = 0; k < 64; k++)
            acc += Wgc[c*128 + s*64 + k] * Wdin[k*66 + j];
        g_M_t[s*66*64 + idx] = acc;
    } else if (idx < 66*64 + 64) {
        int c = idx - 66*64;
        float acc = 0.f;
        for (int k = 0; k < 64; k++)
            acc += Wgc[c*128 + s*64 + k] * bdin[k];
        g_vb[s*64 + c] = acc;
    }
}

// rowsums: g_rs[sb][w] = sum_v A[sb][w][v]
__global__ __launch_bounds__(256) void rowsum_kernel(const float* __restrict__ adj)
{
    const int sb = blockIdx.y;
    const int warp = threadIdx.x >> 5, lane = threadIdx.x & 31;
    const int w = blockIdx.x * 8 + warp;
    const float* Arow = adj + (size_t)sb*1048576 + (size_t)w*1024;
    float a = 0.f;
    #pragma unroll 4
    for (int v = lane; v < 1024; v += 32) a += Arow[v];
    #pragma unroll
    for (int off = 16; off; off >>= 1) a += __shfl_down_sync(0xffffffffu, a, off);
    if (lane == 0) g_rs[sb*1024 + w] = a;
}

// =====================================================================================
// Big diffusion: O[sb][c][w] = sum_v Z[.][c][v] * A[sb][w][v]
// BM=32(ch) x BN=64(w) x BK=32, 256 threads, grid (16,2,4)=128 blocks.
// Per warp: 4 channels via BROADCAST float4 Z read + 64 w via float2 A read.
// stage 0: h->E  1: E->F  2: rh->G  3: G->H
// =====================================================================================
__global__ __launch_bounds__(256) void diffuse64_kernel(const float* __restrict__ adj, int stage)
{
    const int sb = blockIdx.z;
    const int c0 = blockIdx.y * 32;
    const int w0 = blockIdx.x * 64;
    const float* Z; float* O;
    switch (stage) {
        case 0:  Z = g_h   + (sb&1)*65536; O = g_E64 + sb*65536; break;
        case 1:  Z = g_E64 + sb*65536;     O = g_F64 + sb*65536; break;
        case 2:  Z = g_rh  + (sb&1)*65536; O = g_G64 + sb*65536; break;
        default: Z = g_G64 + sb*65536;     O = g_H64 + sb*65536; break;
    }
    const float* A = adj + (size_t)sb*1048576 + (size_t)w0*1024;
    const int tid = threadIdx.x;

    __shared__ float Zs[2][32][36];
    __shared__ float As[2][32][66];

    const int zr = tid >> 3;          // 0..31 channel row in tile
    const int zv = (tid & 7) * 4;     // v offset (one float4)
    const int ar = tid >> 2;          // 0..63 w row
    const int av = (tid & 3) * 8;     // v offset (two float4s)

    const float* Zrow = Z + (size_t)(c0 + zr)*1024;
    const float* Arow = A + (size_t)ar*1024;

    float4 rz, ra0, ra1;
    rz  = *(const float4*)&Zrow[zv];
    ra0 = *(const float4*)&Arow[av];
    ra1 = *(const float4*)&Arow[av + 4];
    Zs[0][zv+0][zr] = rz.x;  Zs[0][zv+1][zr] = rz.y;
    Zs[0][zv+2][zr] = rz.z;  Zs[0][zv+3][zr] = rz.w;
    As[0][av+0][ar] = ra0.x; As[0][av+1][ar] = ra0.y;
    As[0][av+2][ar] = ra0.z; As[0][av+3][ar] = ra0.w;
    As[0][av+4][ar] = ra1.x; As[0][av+5][ar] = ra1.y;
    As[0][av+6][ar] = ra1.z; As[0][av+7][ar] = ra1.w;
    __syncthreads();

    const int cg = (tid >> 5) * 4;    // warp*4 : channel group (broadcast within warp)
    const int wl = (tid & 31) * 2;    // lane w pair
    float acc[4][2] = {};

    int buf = 0;
    for (int kt = 0; kt < 32; kt++) {
        if (kt < 31) {
            const int v0 = (kt + 1) * 32;
            rz  = *(const float4*)&Zrow[v0 + zv];
            ra0 = *(const float4*)&Arow[v0 + av];
            ra1 = *(const float4*)&Arow[v0 + av + 4];
        }
        #pragma unroll
        for (int k = 0; k < 32; k++) {
            float4 z = *(const float4*)&Zs[buf][k][cg];   // broadcast across warp
            float2 a = *(const float2*)&As[buf][k][wl];
            acc[0][0] += z.x*a.x; acc[0][1] += z.x*a.y;
            acc[1][0] += z.y*a.x; acc[1][1] += z.y*a.y;
            acc[2][0] += z.z*a.x; acc[2][1] += z.z*a.y;
            acc[3][0] += z.w*a.x; acc[3][1] += z.w*a.y;
        }
        if (kt < 31) {
            const int nb2 = buf ^ 1;
            Zs[nb2][zv+0][zr] = rz.x;  Zs[nb2][zv+1][zr] = rz.y;
            Zs[nb2][zv+2][zr] = rz.z;  Zs[nb2][zv+3][zr] = rz.w;
            As[nb2][av+0][ar] = ra0.x; As[nb2][av+1][ar] = ra0.y;
            As[nb2][av+2][ar] = ra0.z; As[nb2][av+3][ar] = ra0.w;
            As[nb2][av+4][ar] = ra1.x; As[nb2][av+5][ar] = ra1.y;
            As[nb2][av+6][ar] = ra1.z; As[nb2][av+7][ar] = ra1.w;
        }
        __syncthreads();
        buf ^= 1;
    }
    #pragma unroll
    for (int i = 0; i < 4; i++) {
        *(float2*)&O[(size_t)(c0+cg+i)*1024 + w0 + wl] = make_float2(acc[i][0], acc[i][1]);
    }
}

// =====================================================================================
// 2-channel diffusion. stage 0: z1->Dx  1: z2->Ex  2: Ex->Fx
// grid (128, 4), 256 threads: one w per warp, lanes over v + warp reduce.
// =====================================================================================
__global__ __launch_bounds__(256) void diffuse2_kernel(const float* __restrict__ adj, int stage)
{
    const int sb = blockIdx.y;
    __shared__ float zs[2][NB];
    const float* src;
    if      (stage == 0) src = g_z1 + (sb&1)*2048;
    else if (stage == 1) src = g_z2 + (sb&1)*2048;
    else                 src = g_Ex + sb*2048;
    for (int i = threadIdx.x; i < 2048; i += 256) zs[i >> 10][i & 1023] = src[i];
    __syncthreads();

    const int warp = threadIdx.x >> 5, lane = threadIdx.x & 31;
    const int w = blockIdx.x * 8 + warp;
    const float* Arow = adj + (size_t)sb*1048576 + (size_t)w*1024;
    float a0 = 0.f, a1 = 0.f;
    #pragma unroll 4
    for (int v = lane; v < 1024; v += 32) {
        float av = Arow[v];
        a0 += av * zs[0][v];
        a1 += av * zs[1][v];
    }
    #pragma unroll
    for (int off = 16; off; off >>= 1) {
        a0 += __shfl_down_sync(0xffffffffu, a0, off);
        a1 += __shfl_down_sync(0xffffffffu, a1, off);
    }
    if (lane == 0) {
        float* dst;
        if      (stage == 0) dst = g_Dx + sb*2048;
        else if (stage == 1) dst = g_Ex + sb*2048;
        else                 dst = g_Fx + sb*2048;
        dst[w]        = a0;
        dst[1024 + w] = a1;
    }
}

#define FMA42(acc, w4, v2) do { \
    acc[0][0] += (w4).x*(v2).x; acc[0][1] += (w4).x*(v2).y; \
    acc[1][0] += (w4).y*(v2).x; acc[1][1] += (w4).y*(v2).y; \
    acc[2][0] += (w4).z*(v2).x; acc[2][1] += (w4).z*(v2).y; \
    acc[3][0] += (w4).w*(v2).x; acc[3][1] += (w4).w*(v2).y; } while (0)

// =====================================================================================
// pre kernel: xs1 = Wfs.h + bfs ; preds out ; x1 = m?x:xs1 ; z1 = [x1;m]
// =====================================================================================
__global__ __launch_bounds__(32) void pre_kernel(const float* __restrict__ x,
                                                 const int*   __restrict__ mask,
                                                 const float* __restrict__ Wfs,
                                                 const float* __restrict__ bfs,
                                                 float* __restrict__ out, int t)
{
    const int b  = blockIdx.x >> 5;
    const int nn = (blockIdx.x & 31) * 32 + threadIdx.x;
    float s = bfs[0];
    #pragma unroll 8
    for (int c = 0; c < 64; c++) s += Wfs[c] * g_h[b*65536 + c*1024 + nn];
    out[PRED_OFF + (b*1024 + nn)*12 + t] = s;
    int m = mask[b*12288 + nn*12 + t];
    float xv = x[b*12288 + nn*12 + t];
    float x1 = m ? xv : s;
    g_z1[b*2048 + nn]        = x1;
    g_z1[b*2048 + 1024 + nn] = (float)m;
}

// =====================================================================================
// decoder: out = M0.[Dx0;E0] + M1.[Dx1;E1] + vb0*rs0 + vb1*rs1 + bgc
//          out = prelu(Wlout.[out;h]+blout) ; repr=[out;h] ; xs2=Wro.repr+bro
//          imps out ; z2 = [m?x1:xs2 ; m]
// =====================================================================================
__global__ __launch_bounds__(256) void decoder_kernel(const float* __restrict__ bgc,
                                                      const float* __restrict__ blout,
                                                      const float* __restrict__ Wro,
                                                      const float* __restrict__ bro,
                                                      const float* __restrict__ prelu_a,
                                                      const int*   __restrict__ mask,
                                                      float* __restrict__ out, int t)
{
    const int b  = blockIdx.x >> 5;
    const int n0 = (blockIdx.x & 31) * 32;
    const int tid = threadIdx.x;
    __shared__ float E0s[64][36];
    __shared__ float E1s[64][36];
    __shared__ float Hs[64][36];
    __shared__ float Gs[64][36];
    __shared__ float Os[64][36];
    __shared__ float DXs[2][2][36];
    __shared__ float RSs[2][36];

    for (int i = tid; i < 64*32; i += 256) {
        int r = i >> 5, n = i & 31;
        E0s[r][n] = g_E64[b*65536       + r*1024 + n0 + n];
        E1s[r][n] = g_E64[(2+b)*65536   + r*1024 + n0 + n];
        Hs[r][n]  = g_h  [b*65536       + r*1024 + n0 + n];
    }
    if (tid < 128) {
        int s = tid >> 6, ch = (tid >> 5) & 1, n = tid & 31;
        DXs[s][ch][n] = g_Dx[(s*2 + b)*2048 + ch*1024 + n0 + n];
    } else if (tid < 192) {
        int idx = tid - 128; int s = idx >> 5, n = idx & 31;
        RSs[s][n] = g_rs[(s*2 + b)*1024 + n0 + n];
    }
    __syncthreads();

    const int ty = tid >> 4, tx = tid & 15;
    const int cbv = ty*4, nbv = tx*2;
    float acc[4][2] = {};
    #pragma unroll
    for (int s = 0; s < 2; s++) {
        const float* Mt = g_M_t + s*66*64;
        {
            float4 w0 = *(const float4*)&Mt[0*64 + cbv];
            float2 v0 = *(const float2*)&DXs[s][0][nbv];
            FMA42(acc, w0, v0);
            float4 w1 = *(const float4*)&Mt[1*64 + cbv];
            float2 v1 = *(const float2*)&DXs[s][1][nbv];
            FMA42(acc, w1, v1);
        }
        #pragma unroll 4
        for (int k = 0; k < 64; k++) {
            float4 w = *(const float4*)&Mt[(2+k)*64 + cbv];
            float2 v = s ? *(const float2*)&E1s[k][nbv] : *(const float2*)&E0s[k][nbv];
            FMA42(acc, w, v);
        }
    }
    #pragma unroll
    for (int i = 0; i < 4; i++) {
        int c = cbv + i;
        float v0 = g_vb[c], v1 = g_vb[64 + c], bv = bgc[c];
        Gs[c][nbv]   = acc[i][0] + v0*RSs[0][nbv]   + v1*RSs[1][nbv]   + bv;
        Gs[c][nbv+1] = acc[i][1] + v0*RSs[0][nbv+1] + v1*RSs[1][nbv+1] + bv;
    }
    __syncthreads();

    float acc2[4][2] = {};
    #pragma unroll 4
    for (int k = 0; k < 64; k++) {
        float4 w = *(const float4*)&g_Wlout_t[k*64 + cbv];
        float2 v = *(const float2*)&Gs[k][nbv];
        FMA42(acc2, w, v);
    }
    #pragma unroll 4
    for (int k = 0; k < 64; k++) {
        float4 w = *(const float4*)&g_Wlout_t[(64+k)*64 + cbv];
        float2 v = *(const float2*)&Hs[k][nbv];
        FMA42(acc2, w, v);
    }
    const float pa = prelu_a[0];
    #pragma unroll
    for (int i = 0; i < 4; i++) {
        int c = cbv + i;
        float bv = blout[c];
        float o0 = acc2[i][0] + bv; if (o0 < 0.f) o0 *= pa;
        float o1 = acc2[i][1] + bv; if (o1 < 0.f) o1 *= pa;
        Os[c][nbv] = o0; Os[c][nbv+1] = o1;
        *(float2*)&g_rep[((size_t)(t*2 + b)*128 + c)*1024 + n0 + nbv] = make_float2(o0, o1);
    }
    __syncthreads();

    for (int i = tid; i < 64*32; i += 256) {
        int c = i >> 5, n = i & 31;
        g_rep[((size_t)(t*2 + b)*128 + 64 + c)*1024 + n0 + n] = Hs[c][n];
    }
    if (tid < 32) {
        const int n = tid, nn = n0 + n;
        float s = bro[0];
        #pragma unroll 8
        for (int c = 0; c < 64; c++) s += Wro[c]*Os[c][n] + Wro[64+c]*Hs[c][n];
        out[IMP_OFF + (b*1024 + nn)*12 + t] = s;
        int m = mask[b*12288 + nn*12 + t];
        float x2 = m ? g_z1[b*2048 + nn] : s;
        g_z2[b*2048 + nn]        = x2;
        g_z2[b*2048 + 1024 + nn] = (float)m;
    }
}

// =====================================================================================
// V330 loader (16-wide n-tile). base64: h or rh.
// Row map (330): [z2(2), base64(64)] , per support s: [ex(2), d1(64), fx(2), d2(64)]
// =====================================================================================
__device__ __forceinline__ void load_V330_16(float (*Vs)[17], int b, int n0, int tid,
                                             const float* base64)
{
    for (int i = tid; i < 330*16; i += 256) {
        int r = i >> 4, n = i & 15;
        const float* src;
        const int sb0 = b, sb1 = 2 + b;
        if      (r < 2)   src = g_z2   + b*2048    + r*1024;
        else if (r < 66)  src = base64 + b*65536   + (r-2)*1024;
        else if (r < 68)  src = g_Ex   + sb0*2048  + (r-66)*1024;
        else if (r < 132) src = (base64 == g_h ? g_E64 : g_G64) + sb0*65536 + (r-68)*1024;
        else if (r < 134) src = g_Fx   + sb0*2048  + (r-132)*1024;
        else if (r < 198) src = (base64 == g_h ? g_F64 : g_H64) + sb0*65536 + (r-134)*1024;
        else if (r < 200) src = g_Ex   + sb1*2048  + (r-198)*1024;
        else if (r < 264) src = (base64 == g_h ? g_E64 : g_G64) + sb1*65536 + (r-200)*1024;
        else if (r < 266) src = g_Fx   + sb1*2048  + (r-264)*1024;
        else              src = (base64 == g_h ? g_F64 : g_H64) + sb1*65536 + (r-266)*1024;
        Vs[r][n] = src[n0 + n];
    }
}

__global__ __launch_bounds__(256) void gates_kernel(const float* __restrict__ br,
                                                    const float* __restrict__ bu)
{
    const int b  = blockIdx.x >> 6;
    const int n0 = (blockIdx.x & 63) * 16;
    const int tid = threadIdx.x;
    __shared__ float Vs[330][17];
    load_V330_16(Vs, b, n0, tid, g_h);
    __syncthreads();

    const int ty = tid >> 4, tx = tid & 15;
    const int cbv = ty*4;
    float ar4[4] = {}, au4[4] = {};
    #pragma unroll 5
    for (int k = 0; k < 330; k++) {
        float4 wr = *(const float4*)&g_Wr_t[k*64 + cbv];
        float4 wu = *(const float4*)&g_Wu_t[k*64 + cbv];
        float v = Vs[k][tx];
        ar4[0] += wr.x*v; ar4[1] += wr.y*v; ar4[2] += wr.z*v; ar4[3] += wr.w*v;
        au4[0] += wu.x*v; au4[1] += wu.y*v; au4[2] += wu.z*v; au4[3] += wu.w*v;
    }
    #pragma unroll
    for (int i = 0; i < 4; i++) {
        const int c = cbv + i;
        const size_t idx = (size_t)b*65536 + c*1024 + n0 + tx;
        float hv = g_h[idx];
        float r = 1.f / (1.f + expf(-(ar4[i] + br[c])));
        float u = 1.f / (1.f + expf(-(au4[i] + bu[c])));
        g_u [idx] = u;
        g_rh[idx] = r * hv;
    }
}

__global__ __launch_bounds__(256) void cand_kernel(const float* __restrict__ bc)
{
    const int b  = blockIdx.x >> 6;
    const int n0 = (blockIdx.x & 63) * 16;
    const int tid = threadIdx.x;
    __shared__ float Vs[330][17];
    load_V330_16(Vs, b, n0, tid, g_rh);
    __syncthreads();

    const int ty = tid >> 4, tx = tid & 15;
    const int cbv = ty*4;
    float acc4[4] = {};
    #pragma unroll 5
    for (int k = 0; k < 330; k++) {
        float4 w = *(const float4*)&g_Wc_t[k*64 + cbv];
        float v = Vs[k][tx];
        acc4[0] += w.x*v; acc4[1] += w.y*v; acc4[2] += w.z*v; acc4[3] += w.w*v;
    }
    #pragma unroll
    for (int i = 0; i < 4; i++) {
        const int c = cbv + i;
        const size_t idx = (size_t)b*65536 + c*1024 + n0 + tx;
        float hv = g_h[idx];
        float uv = g_u[idx];
        float cv = tanhf(acc4[i] + bc[c]);
        g_h[idx] = uv*hv + (1.f-uv)*cv;
    }
}

// Final transpose of staged representations: out[b][cc][n][t] = g_rep[t][b][cc][n]
__global__ __launch_bounds__(256) void rep_out_kernel(float* __restrict__ out)
{
    const int bc = blockIdx.x;               // 0..255 = b*128+cc
    const int b = bc >> 7, cc = bc & 127;
    __shared__ float s[12][NB];
    for (int i = threadIdx.x; i < 12*NB; i += 256) {
        int t = i >> 10, n = i & 1023;
        s[t][n] = g_rep[((size_t)(t*2 + b)*128 + cc)*1024 + n];
    }
    __syncthreads();
    float* dst = out + REP_OFF + (size_t)bc * 12288;
    for (int i = threadIdx.x; i < 12288; i += 256) {
        int n = i / 12, t = i - n*12;
        dst[i] = s[t][n];
    }
}

extern "C" void kernel_launch(void* const* d_in, const int* in_sizes, int n_in,
                              void* d_out, int out_size)
{
    const float* x     = (const float*)d_in[0];
    const int*   mask  = (const int*)  d_in[1];
    const float* adj   = (const float*)d_in[2];
    const float* Wr    = (const float*)d_in[3];
    const float* br    = (const float*)d_in[4];
    const float* Wu    = (const float*)d_in[5];
    const float* bu    = (const float*)d_in[6];
    const float* Wc    = (const float*)d_in[7];
    const float* bc    = (const float*)d_in[8];
    const float* Wfs   = (const float*)d_in[9];
    const float* bfs   = (const float*)d_in[10];
    const float* Wdin  = (const float*)d_in[11];
    const float* bdin  = (const float*)d_in[12];
    const float* Wgc   = (const float*)d_in[13];
    const float* bgc   = (const float*)d_in[14];
    const float* Wlout = (const float*)d_in[15];
    const float* blout = (const float*)d_in[16];
    const float* Wro   = (const float*)d_in[17];
    const float* bro   = (const float*)d_in[18];
    const float* pa    = (const float*)d_in[19];
    float* out = (float*)d_out;

    init_h_kernel<<<512, 256>>>();
    prep_weights_kernel<<<83, 256>>>(Wr, Wu, Wc, Wlout);
    prep_M_kernel<<<dim3(17,2), 256>>>(Wgc, Wdin, bdin);
    rowsum_kernel<<<dim3(128,4), 256>>>(adj);

    for (int t = 0; t < 12; t++) {
        pre_kernel<<<64, 32>>>(x, mask, Wfs, bfs, out, t);
        diffuse2_kernel<<<dim3(128,4), 256>>>(adj, 0);          // Dx
        diffuse64_kernel<<<dim3(16,2,4), 256>>>(adj, 0);        // E = A h
        diffuse64_kernel<<<dim3(16,2,4), 256>>>(adj, 1);        // F = A E
        decoder_kernel<<<64, 256>>>(bgc, blout, Wro, bro, pa, mask, out, t);
        diffuse2_kernel<<<dim3(128,4), 256>>>(adj, 1);          // Ex
        diffuse2_kernel<<<dim3(128,4), 256>>>(adj, 2);          // Fx
        gates_kernel<<<128, 256>>>(br, bu);
        diffuse64_kernel<<<dim3(16,2,4), 256>>>(adj, 2);        // G = A rh
        diffuse64_kernel<<<dim3(16,2,4), 256>>>(adj, 3);        // H = A G
        cand_kernel<<<128, 256>>>(bc);
    }
    rep_out_kernel<<<256, 256>>>(out);
}